// round 8
// baseline (speedup 1.0000x reference)
#include <cuda_runtime.h>
#include <math.h>
#include <stdint.h>

#define B_   2
#define S_   2048
#define D_   1024
#define H_   16
#define DH_  64
#define DFF_ 4096
#define M_   (B_*S_)    // 4096 tokens
#define QKVD 3072

// permute k within 16-groups: self-inverse 4x4 transpose
#define PERM16(j) (((j) & ~15) | (((j) & 3) << 2) | (((j) >> 2) & 3))

// ---------------- scratch (static device allocations) ---------------------------
__device__ float g_ln [M_ * D_];
__device__ float g_qkv[(size_t)M_ * QKVD];              // 48 MB
__device__ float g_ctx[M_ * D_];
__device__ float g_h  [M_ * D_];
__device__ float g_ffn[(size_t)M_ * DFF_];              // 64 MB
__device__ float g_pool[12 * 1024 * 1024];              // transposed+perm+rounded weights

// ---------------- helpers --------------------------------------------------------
__device__ __forceinline__ unsigned f2tf32(float x) {
    unsigned r;
    asm("cvt.rna.tf32.f32 %0, %1;" : "=r"(r) : "f"(x));
    return r;
}
__device__ __forceinline__ float rnd_tf32(float x) {
    return __uint_as_float(f2tf32(x));
}
__device__ __forceinline__ void mma_tf32(float* c, const unsigned* a, const unsigned* b) {
    asm volatile(
        "mma.sync.aligned.m16n8k8.row.col.f32.tf32.tf32.f32 "
        "{%0,%1,%2,%3}, {%4,%5,%6,%7}, {%8,%9}, {%0,%1,%2,%3};"
        : "+f"(c[0]), "+f"(c[1]), "+f"(c[2]), "+f"(c[3])
        : "r"(a[0]), "r"(a[1]), "r"(a[2]), "r"(a[3]), "r"(b[0]), "r"(b[1]));
}
__device__ __forceinline__ void cpasync16(float* smem, const float* gmem) {
    unsigned s = (unsigned)__cvta_generic_to_shared(smem);
    asm volatile("cp.async.cg.shared.global [%0], [%1], 16;" :: "r"(s), "l"(gmem));
}

// ---------------- weight prep: out[(rowOff+n)*K + PERM16(k)] = rnd(in[k][n]) ----
__global__ void transpose_round_kernel(const float* __restrict__ in,
                                       float* __restrict__ out,
                                       int K, int N, int rowOff)
{
    __shared__ float t[32][33];
    int k0 = blockIdx.y * 32, n0 = blockIdx.x * 32;
    int tx = threadIdx.x & 31, ty = threadIdx.x >> 5;   // 32 x 8
    #pragma unroll
    for (int r = ty; r < 32; r += 8)
        t[r][tx] = in[(size_t)(k0 + r) * N + n0 + tx];
    __syncthreads();
    #pragma unroll
    for (int r = ty; r < 32; r += 8)
        out[(size_t)(rowOff + n0 + r) * K + PERM16(k0 + tx)] = rnd_tf32(t[tx][r]);
}

// ---------------- LayerNorm (output tf32-rounded, k-permuted) --------------------
__global__ void ln_kernel(const float* __restrict__ x,
                          const float* __restrict__ sc,
                          const float* __restrict__ sh,
                          float* __restrict__ out)
{
    int row = blockIdx.x;
    const float* xr = x + (size_t)row * D_;
    float* outr = out + (size_t)row * D_;

    float s = 0.f, s2 = 0.f;
    for (int j = threadIdx.x; j < D_; j += blockDim.x) {
        float v = xr[j];
        s += v; s2 += v * v;
    }
    __shared__ float rs[256], rs2[256];
    rs[threadIdx.x] = s; rs2[threadIdx.x] = s2;
    __syncthreads();
    for (int o = 128; o > 0; o >>= 1) {
        if (threadIdx.x < o) {
            rs [threadIdx.x] += rs [threadIdx.x + o];
            rs2[threadIdx.x] += rs2[threadIdx.x + o];
        }
        __syncthreads();
    }
    float mean = rs[0] * (1.0f / D_);
    float var  = rs2[0] * (1.0f / D_) - mean * mean;
    float inv  = rsqrtf(var + 1e-5f);
    for (int j = threadIdx.x; j < D_; j += blockDim.x)
        outr[PERM16(j)] = rnd_tf32((xr[j] - mean) * inv * sc[j] + sh[j]);
}

// ---------------- TF32 mma.sync GEMM: perm layout, all-LDS.128 fragments ---------
// C(MxN) = A(MxK) @ W(KxN).  A supplied [m][k-perm]; W supplied [n][k-perm].
// CTA tile 128x128, 4 warps (warp tile 64x64), BK=16, 4-stage cp.async ring.
#define TSW 16                              // tile row stride in floats
#define TILE_F (128 * TSW)                  // 2048 floats per tile
#define STG_FLOATS (2 * TILE_F)             // 4096 floats = 16 KB
#define GSTAGES 4
#define GEMM_SMEM (GSTAGES * STG_FLOATS * 4)   // 64 KB

__global__ __launch_bounds__(128, 2)
void sgemm_tf32_kernel(const float* __restrict__ A,
                       const float* __restrict__ Bt,
                       const float* __restrict__ bias,   // may be null
                       const float* __restrict__ res,    // may be null
                       float* __restrict__ C,
                       int M, int N, int K, int gelu, int roundOut, int permOut)
{
    extern __shared__ float sm[];

    const int tid  = threadIdx.x;
    const int lane = tid & 31;
    const int warp = tid >> 5;       // 0..3
    const int g    = lane >> 2;
    const int t    = lane & 3;
    const int warpRow = warp >> 1;   // 0..1 -> 64 rows
    const int warpCol = warp & 1;    // 0..1 -> 64 cols

    const int rowBase = blockIdx.y * 128;
    const int colBase = blockIdx.x * 128;

    float acc[4][8][4];
    #pragma unroll
    for (int i = 0; i < 4; i++)
        #pragma unroll
        for (int j = 0; j < 8; j++)
            #pragma unroll
            for (int r = 0; r < 4; r++) acc[i][j][r] = 0.f;

    const int nIter = K / 16;

    // staging: A and B tiles are both [128 rows][16 k-perm] contiguous copies.
    // 512 float4 chunks per tile; 128 threads x 4 chunks each.
    #pragma unroll
    for (int p = 0; p < GSTAGES - 1; p++) {
        float* As = sm + p * STG_FLOATS;
        float* Bs = As + TILE_F;
        int k0 = p * 16;
        #pragma unroll
        for (int u = 0; u < 4; u++) {
            int idx = u * 128 + tid;
            int r = idx >> 2, c = (idx & 3) * 4;
            cpasync16(&As[r * TSW + c], &A [(size_t)(rowBase + r) * K + k0 + c]);
            cpasync16(&Bs[r * TSW + c], &Bt[(size_t)(colBase + r) * K + k0 + c]);
        }
        asm volatile("cp.async.commit_group;");
    }

    for (int kt = 0; kt < nIter; ++kt) {
        if (kt + 3 <= nIter)      { asm volatile("cp.async.wait_group 2;"); }
        else if (kt + 2 == nIter) { asm volatile("cp.async.wait_group 1;"); }
        else                      { asm volatile("cp.async.wait_group 0;"); }
        __syncthreads();

        if (kt + 3 < nIter) {
            float* As = sm + ((kt + 3) & 3) * STG_FLOATS;
            float* Bs = As + TILE_F;
            int k0 = (kt + 3) * 16;
            #pragma unroll
            for (int u = 0; u < 4; u++) {
                int idx = u * 128 + tid;
                int r = idx >> 2, c = (idx & 3) * 4;
                cpasync16(&As[r * TSW + c], &A [(size_t)(rowBase + r) * K + k0 + c]);
                cpasync16(&Bs[r * TSW + c], &Bt[(size_t)(colBase + r) * K + k0 + c]);
            }
            asm volatile("cp.async.commit_group;");
        }

        const float* As_ = sm + (kt & 3) * STG_FLOATS;
        const float* Bs_ = As_ + TILE_F;

        // one LDS.128 per fragment-row: covers k = {t, t+4, t+8, t+12}
        float4 af[4][2];
        #pragma unroll
        for (int mt = 0; mt < 4; mt++) {
            int m = warpRow * 64 + mt * 16 + g;
            af[mt][0] = *(const float4*)&As_[m * TSW + 4 * t];
            af[mt][1] = *(const float4*)&As_[(m + 8) * TSW + 4 * t];
        }
        float4 bf[8];
        #pragma unroll
        for (int nt = 0; nt < 8; nt++) {
            int n = warpCol * 64 + nt * 8 + g;
            bf[nt] = *(const float4*)&Bs_[n * TSW + 4 * t];
        }

        // ks = 0: k = {t, t+4}
        #pragma unroll
        for (int mt = 0; mt < 4; mt++) {
            unsigned a0[4] = { __float_as_uint(af[mt][0].x), __float_as_uint(af[mt][1].x),
                               __float_as_uint(af[mt][0].y), __float_as_uint(af[mt][1].y) };
            #pragma unroll
            for (int nt = 0; nt < 8; nt++) {
                unsigned b0[2] = { __float_as_uint(bf[nt].x), __float_as_uint(bf[nt].y) };
                mma_tf32(acc[mt][nt], a0, b0);
            }
        }
        // ks = 1: k = {t+8, t+12}
        #pragma unroll
        for (int mt = 0; mt < 4; mt++) {
            unsigned a1[4] = { __float_as_uint(af[mt][0].z), __float_as_uint(af[mt][1].z),
                               __float_as_uint(af[mt][0].w), __float_as_uint(af[mt][1].w) };
            #pragma unroll
            for (int nt = 0; nt < 8; nt++) {
                unsigned b1[2] = { __float_as_uint(bf[nt].z), __float_as_uint(bf[nt].w) };
                mma_tf32(acc[mt][nt], a1, b1);
            }
        }
    }

    #pragma unroll
    for (int mt = 0; mt < 4; mt++) {
        #pragma unroll
        for (int nt = 0; nt < 8; nt++) {
            int r0 = rowBase + warpRow * 64 + mt * 16 + g;
            int c0 = colBase + warpCol * 64 + nt * 8 + 2 * t;
            #pragma unroll
            for (int half = 0; half < 2; half++) {
                int r = r0 + half * 8;
                float v0 = acc[mt][nt][2*half], v1 = acc[mt][nt][2*half+1];
                if (bias) { v0 += bias[c0]; v1 += bias[c0 + 1]; }
                if (gelu) {
                    float t0 = 1.5957691216057308f * v0 + 0.0713548162726009f * v0 * v0 * v0;
                    v0 = __fdividef(v0, 1.f + __expf(-t0));
                    float t1 = 1.5957691216057308f * v1 + 0.0713548162726009f * v1 * v1 * v1;
                    v1 = __fdividef(v1, 1.f + __expf(-t1));
                }
                if (res) {
                    float2 rr = *(const float2*)&res[(size_t)r * N + c0];
                    v0 += rr.x; v1 += rr.y;
                }
                if (roundOut) { v0 = rnd_tf32(v0); v1 = rnd_tf32(v1); }
                if (permOut) {
                    C[(size_t)r * N + PERM16(c0)]     = v0;
                    C[(size_t)r * N + PERM16(c0 + 1)] = v1;
                } else {
                    *(float2*)&C[(size_t)r * N + c0] = make_float2(v0, v1);
                }
            }
        }
    }
}

// ---------------- fused flash attention (causal, tf32 mma.sync) ------------------
// K/V double-buffered with prefetch overlap. Q scaled by 1/8 in frags.
// ctx output written k-PERMUTED (feeds O-proj GEMM as A operand).
#define SK 68
#define SV 72
#define KVBUF (64*SK + 64*SV)
#define FLASH_SMEM ((128*SK + 2*KVBUF) * 4)

__global__ __launch_bounds__(256)
void flash_attn_kernel(const float* __restrict__ qkv, float* __restrict__ ctx)
{
    extern __shared__ float sm[];
    float* Ps = sm;                       // 128 x SK (Q prologue, then P)
    float* KV0 = sm + 128 * SK;           // double-buffered K/V tiles

    const int qt = (int)(gridDim.x - 1) - (int)blockIdx.x;   // big tiles first
    const int bh = blockIdx.y;
    const int b = bh >> 4, h = bh & 15;
    const float* qb = qkv + (size_t)b * S_ * QKVD + h * DH_;
    const float* kb = qb + D_;
    const float* vb = qb + 2 * D_;
    float* cb = ctx + (size_t)b * S_ * D_ + h * DH_;

    const int tid = threadIdx.x, lane = tid & 31, warp = tid >> 5;
    const int g = lane >> 2, t = lane & 3;
    const int rowBase = qt * 128;
    const int wrow = warp * 16;
    const int ktmax = 2 * qt + 2;

    // ---- Q prologue
    #pragma unroll
    for (int u = 0; u < 8; u++) {
        int idx = u * 32 + lane;
        int r = idx >> 4, c4 = (idx & 15) * 4;
        cpasync16(&Ps[(wrow + r) * SK + c4],
                  &qb[(size_t)(rowBase + wrow + r) * QKVD + c4]);
    }
    asm volatile("cp.async.commit_group;");
    asm volatile("cp.async.wait_group 0;");
    __syncwarp();

    unsigned qa[8][4];
    #pragma unroll
    for (int ks = 0; ks < 8; ks++) {
        qa[ks][0] = __float_as_uint(0.125f * Ps[(wrow + g)     * SK + 8*ks + t]);
        qa[ks][1] = __float_as_uint(0.125f * Ps[(wrow + g + 8) * SK + 8*ks + t]);
        qa[ks][2] = __float_as_uint(0.125f * Ps[(wrow + g)     * SK + 8*ks + t + 4]);
        qa[ks][3] = __float_as_uint(0.125f * Ps[(wrow + g + 8) * SK + 8*ks + t + 4]);
    }

    // ---- prefetch KV tile 0 into buffer 0
    {
        float* Ks = KV0;
        float* Vs = KV0 + 64 * SK;
        #pragma unroll
        for (int u = 0; u < 4; u++) {
            int idx = u * 256 + tid;
            int r = idx >> 4, c4 = (idx & 15) * 4;
            cpasync16(&Ks[r * SK + c4], &kb[(size_t)r * QKVD + c4]);
            cpasync16(&Vs[r * SV + c4], &vb[(size_t)r * QKVD + c4]);
        }
        asm volatile("cp.async.commit_group;");
    }

    float o[8][4];
    #pragma unroll
    for (int nt = 0; nt < 8; nt++)
        #pragma unroll
        for (int e = 0; e < 4; e++) o[nt][e] = 0.f;
    float m0 = -1e30f, m1 = -1e30f, l0 = 0.f, l1 = 0.f;
    const int row0 = rowBase + wrow + g, row1 = row0 + 8;

    for (int kt = 0; kt < ktmax; kt++) {
        __syncthreads();                       // prev compute done on buf^1
        if (kt + 1 < ktmax) {                  // prefetch next tile into buf^1
            float* Ks = KV0 + ((kt + 1) & 1) * KVBUF;
            float* Vs = Ks + 64 * SK;
            #pragma unroll
            for (int u = 0; u < 4; u++) {
                int idx = u * 256 + tid;
                int r = idx >> 4, c4 = (idx & 15) * 4;
                cpasync16(&Ks[r * SK + c4], &kb[(size_t)((kt + 1) * 64 + r) * QKVD + c4]);
                cpasync16(&Vs[r * SV + c4], &vb[(size_t)((kt + 1) * 64 + r) * QKVD + c4]);
            }
            asm volatile("cp.async.commit_group;");
            asm volatile("cp.async.wait_group 1;");
        } else {
            asm volatile("cp.async.wait_group 0;");
        }
        __syncthreads();                       // tile kt visible to all

        const float* Ks = KV0 + (kt & 1) * KVBUF;
        const float* Vs = Ks + 64 * SK;

        // ---- S = Q K^T (Q pre-scaled)
        float sc[8][4];
        #pragma unroll
        for (int nt = 0; nt < 8; nt++) {
            sc[nt][0] = sc[nt][1] = sc[nt][2] = sc[nt][3] = 0.f;
            #pragma unroll
            for (int ks = 0; ks < 8; ks++) {
                unsigned bb[2];
                bb[0] = __float_as_uint(Ks[(8*nt + g) * SK + 8*ks + t]);
                bb[1] = __float_as_uint(Ks[(8*nt + g) * SK + 8*ks + t + 4]);
                mma_tf32(sc[nt], qa[ks], bb);
            }
        }

        float mx0 = -1e30f, mx1 = -1e30f;
        const int colb = kt * 64 + 2 * t;
        #pragma unroll
        for (int nt = 0; nt < 8; nt++) {
            int c0 = colb + 8 * nt;
            float v0 = sc[nt][0]; if (c0     > row0) v0 = -1e30f;
            float v1 = sc[nt][1]; if (c0 + 1 > row0) v1 = -1e30f;
            float v2 = sc[nt][2]; if (c0     > row1) v2 = -1e30f;
            float v3 = sc[nt][3]; if (c0 + 1 > row1) v3 = -1e30f;
            sc[nt][0] = v0; sc[nt][1] = v1; sc[nt][2] = v2; sc[nt][3] = v3;
            mx0 = fmaxf(mx0, fmaxf(v0, v1));
            mx1 = fmaxf(mx1, fmaxf(v2, v3));
        }
        mx0 = fmaxf(mx0, __shfl_xor_sync(0xffffffffu, mx0, 1));
        mx0 = fmaxf(mx0, __shfl_xor_sync(0xffffffffu, mx0, 2));
        mx1 = fmaxf(mx1, __shfl_xor_sync(0xffffffffu, mx1, 1));
        mx1 = fmaxf(mx1, __shfl_xor_sync(0xffffffffu, mx1, 2));

        float mn0 = fmaxf(m0, mx0), mn1 = fmaxf(m1, mx1);
        float s0 = __expf(m0 - mn0), s1 = __expf(m1 - mn1);
        m0 = mn0; m1 = mn1;

        float sum0 = 0.f, sum1 = 0.f;
        #pragma unroll
        for (int nt = 0; nt < 8; nt++) {
            float p0 = __expf(sc[nt][0] - mn0);
            float p1 = __expf(sc[nt][1] - mn0);
            float p2 = __expf(sc[nt][2] - mn1);
            float p3 = __expf(sc[nt][3] - mn1);
            sum0 += p0 + p1; sum1 += p2 + p3;
            *(float2*)&Ps[(wrow + g)     * SK + 8*nt + 2*t] =
                make_float2(rnd_tf32(p0), rnd_tf32(p1));
            *(float2*)&Ps[(wrow + g + 8) * SK + 8*nt + 2*t] =
                make_float2(rnd_tf32(p2), rnd_tf32(p3));
        }
        sum0 += __shfl_xor_sync(0xffffffffu, sum0, 1);
        sum0 += __shfl_xor_sync(0xffffffffu, sum0, 2);
        sum1 += __shfl_xor_sync(0xffffffffu, sum1, 1);
        sum1 += __shfl_xor_sync(0xffffffffu, sum1, 2);
        l0 = l0 * s0 + sum0;
        l1 = l1 * s1 + sum1;

        #pragma unroll
        for (int nt = 0; nt < 8; nt++) {
            o[nt][0] *= s0; o[nt][1] *= s0;
            o[nt][2] *= s1; o[nt][3] *= s1;
        }
        __syncwarp();                          // P visible within warp

        // ---- O += P @ V
        #pragma unroll
        for (int ks = 0; ks < 8; ks++) {
            unsigned pa[4];
            pa[0] = __float_as_uint(Ps[(wrow + g)     * SK + 8*ks + t]);
            pa[1] = __float_as_uint(Ps[(wrow + g + 8) * SK + 8*ks + t]);
            pa[2] = __float_as_uint(Ps[(wrow + g)     * SK + 8*ks + t + 4]);
            pa[3] = __float_as_uint(Ps[(wrow + g + 8) * SK + 8*ks + t + 4]);
            #pragma unroll
            for (int nt = 0; nt < 8; nt++) {
                unsigned bb[2];
                bb[0] = __float_as_uint(Vs[(8*ks + t)     * SV + 8*nt + g]);
                bb[1] = __float_as_uint(Vs[(8*ks + t + 4) * SV + 8*nt + g]);
                mma_tf32(o[nt], pa, bb);
            }
        }
    }

    // epilogue: tf32-rounded, k-PERMUTED stores (ctx feeds O-proj GEMM)
    float inv0 = __fdividef(1.f, l0), inv1 = __fdividef(1.f, l1);
    #pragma unroll
    for (int nt = 0; nt < 8; nt++) {
        int c0 = 8 * nt + 2 * t;
        cb[(size_t)row0 * D_ + PERM16(c0)]     = rnd_tf32(o[nt][0] * inv0);
        cb[(size_t)row0 * D_ + PERM16(c0 + 1)] = rnd_tf32(o[nt][1] * inv0);
        cb[(size_t)row1 * D_ + PERM16(c0)]     = rnd_tf32(o[nt][2] * inv1);
        cb[(size_t)row1 * D_ + PERM16(c0 + 1)] = rnd_tf32(o[nt][3] * inv1);
    }
}

// ---------------- launcher -------------------------------------------------------
extern "C" void kernel_launch(void* const* d_in, const int* in_sizes, int n_in,
                              void* d_out, int out_size)
{
    const float* x     = (const float*)d_in[0];
    const float* ln1_s = (const float*)d_in[1];
    const float* ln1_b = (const float*)d_in[2];
    const float* wq    = (const float*)d_in[3];
    const float* wk    = (const float*)d_in[4];
    const float* wv    = (const float*)d_in[5];
    const float* wo    = (const float*)d_in[6];
    const float* bo    = (const float*)d_in[7];
    const float* ln2_s = (const float*)d_in[8];
    const float* ln2_b = (const float*)d_in[9];
    const float* w1    = (const float*)d_in[10];
    const float* b1    = (const float*)d_in[11];
    const float* w2    = (const float*)d_in[12];
    const float* b2    = (const float*)d_in[13];
    float* out = (float*)d_out;

    float *ln, *qkv, *ctx, *h, *ffn, *pool;
    cudaGetSymbolAddress((void**)&ln,   g_ln);
    cudaGetSymbolAddress((void**)&qkv,  g_qkv);
    cudaGetSymbolAddress((void**)&ctx,  g_ctx);
    cudaGetSymbolAddress((void**)&h,    g_h);
    cudaGetSymbolAddress((void**)&ffn,  g_ffn);
    cudaGetSymbolAddress((void**)&pool, g_pool);

    const int MB = 1024 * 1024;
    float* wqkvT = pool + 0 * MB;   // [3072][1024] perm
    float* woT   = pool + 3 * MB;   // [1024][1024] perm
    float* w1T   = pool + 4 * MB;   // [4096][1024] perm
    float* w2T   = pool + 8 * MB;   // [1024][4096] perm

    cudaFuncSetAttribute(flash_attn_kernel,
                         cudaFuncAttributeMaxDynamicSharedMemorySize, FLASH_SMEM);
    cudaFuncSetAttribute(sgemm_tf32_kernel,
                         cudaFuncAttributeMaxDynamicSharedMemorySize, GEMM_SMEM);

    // 0) weight prep: transpose + perm + round (QKV packed into [3072][1024])
    transpose_round_kernel<<<dim3(D_/32,  D_/32),  256>>>(wq, wqkvT, D_, D_, 0);
    transpose_round_kernel<<<dim3(D_/32,  D_/32),  256>>>(wk, wqkvT, D_, D_, 1024);
    transpose_round_kernel<<<dim3(D_/32,  D_/32),  256>>>(wv, wqkvT, D_, D_, 2048);
    transpose_round_kernel<<<dim3(D_/32,  D_/32),  256>>>(wo, woT,  D_, D_, 0);
    transpose_round_kernel<<<dim3(DFF_/32, D_/32), 256>>>(w1, w1T,  D_, DFF_, 0);
    transpose_round_kernel<<<dim3(D_/32, DFF_/32), 256>>>(w2, w2T,  DFF_, D_, 0);

    // 1) ln1(x) -> perm
    ln_kernel<<<M_, 256>>>(x, ln1_s, ln1_b, ln);

    // 2) fused QKV projection: A=ln(perm), B=wqkvT(perm); out NORMAL (+round)
    dim3 gqkv(QKVD / 128, M_ / 128);
    sgemm_tf32_kernel<<<gqkv, 128, GEMM_SMEM>>>(ln, wqkvT, nullptr, nullptr, qkv,
                                                M_, QKVD, D_, 0, 1, 0);

    // 3) fused flash attention -> ctx (rounded + perm)
    flash_attn_kernel<<<dim3(S_/128, B_*H_), 256, FLASH_SMEM>>>(qkv, ctx);

    // 4) output projection + bias + residual -> h (normal, full precision)
    dim3 gp(D_ / 128, M_ / 128);
    sgemm_tf32_kernel<<<gp, 128, GEMM_SMEM>>>(ctx, woT, bo, x, h, M_, D_, D_, 0, 0, 0);

    // 5) ln2(h) -> perm
    ln_kernel<<<M_, 256>>>(h, ln2_s, ln2_b, ln);

    // 6) FFN: ffn written rounded+perm (feeds FFN2 as A); final out normal
    dim3 gf1(DFF_ / 128, M_ / 128);
    sgemm_tf32_kernel<<<gf1, 128, GEMM_SMEM>>>(ln, w1T, b1, nullptr, ffn, M_, DFF_, D_, 1, 1, 1);
    sgemm_tf32_kernel<<<gp, 128, GEMM_SMEM>>>(ffn, w2T, b2, h, out, M_, D_, DFF_, 0, 0, 0);
}

// round 9
// speedup vs baseline: 1.0443x; 1.0443x over previous
#include <cuda_runtime.h>
#include <math.h>
#include <stdint.h>

#define B_   2
#define S_   2048
#define D_   1024
#define H_   16
#define DH_  64
#define DFF_ 4096
#define M_   (B_*S_)    // 4096 tokens
#define QKVD 3072

// position of original k within its 8-group: pairs (t, t+4) adjacent
#define POS8(j) (((j) & ~7) | (((j) & 3) << 1) | (((j) >> 2) & 1))

// ---------------- scratch (static device allocations) ---------------------------
__device__ float g_ln [M_ * D_];
__device__ float g_qkv[(size_t)M_ * QKVD];              // 48 MB
__device__ float g_ctx[M_ * D_];
__device__ float g_h  [M_ * D_];
__device__ float g_ffn[(size_t)M_ * DFF_];              // 64 MB
__device__ float g_pool[12 * 1024 * 1024];              // transposed+perm+rounded weights

// ---------------- helpers --------------------------------------------------------
__device__ __forceinline__ unsigned f2tf32(float x) {
    unsigned r;
    asm("cvt.rna.tf32.f32 %0, %1;" : "=r"(r) : "f"(x));
    return r;
}
__device__ __forceinline__ float rnd_tf32(float x) {
    return __uint_as_float(f2tf32(x));
}
__device__ __forceinline__ void mma_tf32(float* c, const unsigned* a, const unsigned* b) {
    asm volatile(
        "mma.sync.aligned.m16n8k8.row.col.f32.tf32.tf32.f32 "
        "{%0,%1,%2,%3}, {%4,%5,%6,%7}, {%8,%9}, {%0,%1,%2,%3};"
        : "+f"(c[0]), "+f"(c[1]), "+f"(c[2]), "+f"(c[3])
        : "r"(a[0]), "r"(a[1]), "r"(a[2]), "r"(a[3]), "r"(b[0]), "r"(b[1]));
}
__device__ __forceinline__ void cpasync16(float* smem, const float* gmem) {
    unsigned s = (unsigned)__cvta_generic_to_shared(smem);
    asm volatile("cp.async.cg.shared.global [%0], [%1], 16;" :: "r"(s), "l"(gmem));
}

// ---------------- weight prep: out[(rowOff+n)*K + POS8(k)] = rnd(in[k][n]) ------
__global__ void transpose_round_kernel(const float* __restrict__ in,
                                       float* __restrict__ out,
                                       int K, int N, int rowOff)
{
    __shared__ float t[32][33];
    int k0 = blockIdx.y * 32, n0 = blockIdx.x * 32;
    int tx = threadIdx.x & 31, ty = threadIdx.x >> 5;   // 32 x 8
    #pragma unroll
    for (int r = ty; r < 32; r += 8)
        t[r][tx] = in[(size_t)(k0 + r) * N + n0 + tx];
    __syncthreads();
    #pragma unroll
    for (int r = ty; r < 32; r += 8)
        out[(size_t)(rowOff + n0 + r) * K + POS8(k0 + tx)] = rnd_tf32(t[tx][r]);
}

// ---------------- LayerNorm (output tf32-rounded, k pair-permuted) ---------------
__global__ void ln_kernel(const float* __restrict__ x,
                          const float* __restrict__ sc,
                          const float* __restrict__ sh,
                          float* __restrict__ out)
{
    int row = blockIdx.x;
    const float* xr = x + (size_t)row * D_;
    float* outr = out + (size_t)row * D_;

    float s = 0.f, s2 = 0.f;
    for (int j = threadIdx.x; j < D_; j += blockDim.x) {
        float v = xr[j];
        s += v; s2 += v * v;
    }
    __shared__ float rs[256], rs2[256];
    rs[threadIdx.x] = s; rs2[threadIdx.x] = s2;
    __syncthreads();
    for (int o = 128; o > 0; o >>= 1) {
        if (threadIdx.x < o) {
            rs [threadIdx.x] += rs [threadIdx.x + o];
            rs2[threadIdx.x] += rs2[threadIdx.x + o];
        }
        __syncthreads();
    }
    float mean = rs[0] * (1.0f / D_);
    float var  = rs2[0] * (1.0f / D_) - mean * mean;
    float inv  = rsqrtf(var + 1e-5f);
    for (int j = threadIdx.x; j < D_; j += blockDim.x)
        outr[POS8(j)] = rnd_tf32((xr[j] - mean) * inv * sc[j] + sh[j]);
}

// ---------------- TF32 mma.sync GEMM: pair-perm layout, LDS.64 fragments ---------
// C(MxN) = A(MxK) @ W(KxN).  A supplied [m][k-pos8]; W supplied [n][k-pos8].
// CTA tile 128x128, 4 warps (warp tile 64x64), BK=16, 4-stage cp.async ring.
// Tile rows stride 24 floats: per-phase bank starts {0,8,16,24}+2t -> conflict-free.
#define TSW 24
#define TILE_F (128 * TSW)                  // 3072 floats
#define STG_FLOATS (2 * TILE_F)             // 6144 floats = 24 KB
#define GSTAGES 4
#define GEMM_SMEM (GSTAGES * STG_FLOATS * 4)   // 96 KB

__global__ __launch_bounds__(128, 2)
void sgemm_tf32_kernel(const float* __restrict__ A,
                       const float* __restrict__ Bt,
                       const float* __restrict__ bias,   // may be null
                       const float* __restrict__ res,    // may be null
                       float* __restrict__ C,
                       int M, int N, int K, int gelu, int roundOut, int permOut)
{
    extern __shared__ float sm[];

    const int tid  = threadIdx.x;
    const int lane = tid & 31;
    const int warp = tid >> 5;       // 0..3
    const int g    = lane >> 2;
    const int t    = lane & 3;
    const int warpRow = warp >> 1;   // 0..1 -> 64 rows
    const int warpCol = warp & 1;    // 0..1 -> 64 cols

    const int rowBase = blockIdx.y * 128;
    const int colBase = blockIdx.x * 128;

    float acc[4][8][4];
    #pragma unroll
    for (int i = 0; i < 4; i++)
        #pragma unroll
        for (int j = 0; j < 8; j++)
            #pragma unroll
            for (int r = 0; r < 4; r++) acc[i][j][r] = 0.f;

    const int nIter = K / 16;

    // staging: A and B tiles both [128 rows][16 floats] at stride 24 (straight copy;
    // gmem rows are already pos8-permuted by producers / prep).
    #pragma unroll
    for (int p = 0; p < GSTAGES - 1; p++) {
        float* As = sm + p * STG_FLOATS;
        float* Bs = As + TILE_F;
        int k0 = p * 16;
        #pragma unroll
        for (int u = 0; u < 4; u++) {
            int idx = u * 128 + tid;
            int r = idx >> 2, c = (idx & 3) * 4;
            cpasync16(&As[r * TSW + c], &A [(size_t)(rowBase + r) * K + k0 + c]);
            cpasync16(&Bs[r * TSW + c], &Bt[(size_t)(colBase + r) * K + k0 + c]);
        }
        asm volatile("cp.async.commit_group;");
    }

    for (int kt = 0; kt < nIter; ++kt) {
        if (kt + 3 <= nIter)      { asm volatile("cp.async.wait_group 2;"); }
        else if (kt + 2 == nIter) { asm volatile("cp.async.wait_group 1;"); }
        else                      { asm volatile("cp.async.wait_group 0;"); }
        __syncthreads();

        if (kt + 3 < nIter) {
            float* As = sm + ((kt + 3) & 3) * STG_FLOATS;
            float* Bs = As + TILE_F;
            int k0 = (kt + 3) * 16;
            #pragma unroll
            for (int u = 0; u < 4; u++) {
                int idx = u * 128 + tid;
                int r = idx >> 2, c = (idx & 3) * 4;
                cpasync16(&As[r * TSW + c], &A [(size_t)(rowBase + r) * K + k0 + c]);
                cpasync16(&Bs[r * TSW + c], &Bt[(size_t)(colBase + r) * K + k0 + c]);
            }
            asm volatile("cp.async.commit_group;");
        }

        const float* As_ = sm + (kt & 3) * STG_FLOATS;
        const float* Bs_ = As_ + TILE_F;

        #pragma unroll
        for (int ks = 0; ks < 2; ks++) {
            const int kp = ks * 8 + 2 * t;          // pair (k=t, k=t+4) adjacent
            unsigned afr[4][4], bfr[8][2];
            #pragma unroll
            for (int mt = 0; mt < 4; mt++) {
                int m = warpRow * 64 + mt * 16 + g;
                float2 p0 = *(const float2*)&As_[m * TSW + kp];
                float2 p1 = *(const float2*)&As_[(m + 8) * TSW + kp];
                afr[mt][0] = __float_as_uint(p0.x);
                afr[mt][1] = __float_as_uint(p1.x);
                afr[mt][2] = __float_as_uint(p0.y);
                afr[mt][3] = __float_as_uint(p1.y);
            }
            #pragma unroll
            for (int nt = 0; nt < 8; nt++) {
                int n = warpCol * 64 + nt * 8 + g;
                float2 q = *(const float2*)&Bs_[n * TSW + kp];
                bfr[nt][0] = __float_as_uint(q.x);
                bfr[nt][1] = __float_as_uint(q.y);
            }
            #pragma unroll
            for (int mt = 0; mt < 4; mt++)
                #pragma unroll
                for (int nt = 0; nt < 8; nt++)
                    mma_tf32(acc[mt][nt], afr[mt], bfr[nt]);
        }
    }

    #pragma unroll
    for (int mt = 0; mt < 4; mt++) {
        #pragma unroll
        for (int nt = 0; nt < 8; nt++) {
            int r0 = rowBase + warpRow * 64 + mt * 16 + g;
            int c0 = colBase + warpCol * 64 + nt * 8 + 2 * t;
            #pragma unroll
            for (int half = 0; half < 2; half++) {
                int r = r0 + half * 8;
                float v0 = acc[mt][nt][2*half], v1 = acc[mt][nt][2*half+1];
                if (bias) { v0 += bias[c0]; v1 += bias[c0 + 1]; }
                if (gelu) {
                    float t0 = 1.5957691216057308f * v0 + 0.0713548162726009f * v0 * v0 * v0;
                    v0 = __fdividef(v0, 1.f + __expf(-t0));
                    float t1 = 1.5957691216057308f * v1 + 0.0713548162726009f * v1 * v1 * v1;
                    v1 = __fdividef(v1, 1.f + __expf(-t1));
                }
                if (res) {
                    float2 rr = *(const float2*)&res[(size_t)r * N + c0];
                    v0 += rr.x; v1 += rr.y;
                }
                if (roundOut) { v0 = rnd_tf32(v0); v1 = rnd_tf32(v1); }
                if (permOut) {
                    C[(size_t)r * N + POS8(c0)]     = v0;
                    C[(size_t)r * N + POS8(c0 + 1)] = v1;
                } else {
                    *(float2*)&C[(size_t)r * N + c0] = make_float2(v0, v1);
                }
            }
        }
    }
}

// ---------------- fused flash attention (causal, tf32 mma.sync) ------------------
// K/V double-buffered with prefetch overlap. Q scaled by 1/8 in frags.
// ctx written tf32-rounded + pos8-permuted (feeds O-proj GEMM as A operand).
#define SK 68
#define SV 72
#define KVBUF (64*SK + 64*SV)
#define FLASH_SMEM ((128*SK + 2*KVBUF) * 4)

__global__ __launch_bounds__(256)
void flash_attn_kernel(const float* __restrict__ qkv, float* __restrict__ ctx)
{
    extern __shared__ float sm[];
    float* Ps = sm;                       // 128 x SK (Q prologue, then P)
    float* KV0 = sm + 128 * SK;           // double-buffered K/V tiles

    const int qt = (int)(gridDim.x - 1) - (int)blockIdx.x;   // big tiles first
    const int bh = blockIdx.y;
    const int b = bh >> 4, h = bh & 15;
    const float* qb = qkv + (size_t)b * S_ * QKVD + h * DH_;
    const float* kb = qb + D_;
    const float* vb = qb + 2 * D_;
    float* cb = ctx + (size_t)b * S_ * D_ + h * DH_;

    const int tid = threadIdx.x, lane = tid & 31, warp = tid >> 5;
    const int g = lane >> 2, t = lane & 3;
    const int rowBase = qt * 128;
    const int wrow = warp * 16;
    const int ktmax = 2 * qt + 2;

    // ---- Q prologue
    #pragma unroll
    for (int u = 0; u < 8; u++) {
        int idx = u * 32 + lane;
        int r = idx >> 4, c4 = (idx & 15) * 4;
        cpasync16(&Ps[(wrow + r) * SK + c4],
                  &qb[(size_t)(rowBase + wrow + r) * QKVD + c4]);
    }
    asm volatile("cp.async.commit_group;");
    asm volatile("cp.async.wait_group 0;");
    __syncwarp();

    unsigned qa[8][4];
    #pragma unroll
    for (int ks = 0; ks < 8; ks++) {
        qa[ks][0] = __float_as_uint(0.125f * Ps[(wrow + g)     * SK + 8*ks + t]);
        qa[ks][1] = __float_as_uint(0.125f * Ps[(wrow + g + 8) * SK + 8*ks + t]);
        qa[ks][2] = __float_as_uint(0.125f * Ps[(wrow + g)     * SK + 8*ks + t + 4]);
        qa[ks][3] = __float_as_uint(0.125f * Ps[(wrow + g + 8) * SK + 8*ks + t + 4]);
    }

    // ---- prefetch KV tile 0 into buffer 0
    {
        float* Ks = KV0;
        float* Vs = KV0 + 64 * SK;
        #pragma unroll
        for (int u = 0; u < 4; u++) {
            int idx = u * 256 + tid;
            int r = idx >> 4, c4 = (idx & 15) * 4;
            cpasync16(&Ks[r * SK + c4], &kb[(size_t)r * QKVD + c4]);
            cpasync16(&Vs[r * SV + c4], &vb[(size_t)r * QKVD + c4]);
        }
        asm volatile("cp.async.commit_group;");
    }

    float o[8][4];
    #pragma unroll
    for (int nt = 0; nt < 8; nt++)
        #pragma unroll
        for (int e = 0; e < 4; e++) o[nt][e] = 0.f;
    float m0 = -1e30f, m1 = -1e30f, l0 = 0.f, l1 = 0.f;
    const int row0 = rowBase + wrow + g, row1 = row0 + 8;

    for (int kt = 0; kt < ktmax; kt++) {
        __syncthreads();                       // prev compute done on buf^1
        if (kt + 1 < ktmax) {                  // prefetch next tile into buf^1
            float* Ks = KV0 + ((kt + 1) & 1) * KVBUF;
            float* Vs = Ks + 64 * SK;
            #pragma unroll
            for (int u = 0; u < 4; u++) {
                int idx = u * 256 + tid;
                int r = idx >> 4, c4 = (idx & 15) * 4;
                cpasync16(&Ks[r * SK + c4], &kb[(size_t)((kt + 1) * 64 + r) * QKVD + c4]);
                cpasync16(&Vs[r * SV + c4], &vb[(size_t)((kt + 1) * 64 + r) * QKVD + c4]);
            }
            asm volatile("cp.async.commit_group;");
            asm volatile("cp.async.wait_group 1;");
        } else {
            asm volatile("cp.async.wait_group 0;");
        }
        __syncthreads();                       // tile kt visible to all

        const float* Ks = KV0 + (kt & 1) * KVBUF;
        const float* Vs = Ks + 64 * SK;

        // ---- S = Q K^T (Q pre-scaled)
        float sc[8][4];
        #pragma unroll
        for (int nt = 0; nt < 8; nt++) {
            sc[nt][0] = sc[nt][1] = sc[nt][2] = sc[nt][3] = 0.f;
            #pragma unroll
            for (int ks = 0; ks < 8; ks++) {
                unsigned bb[2];
                bb[0] = __float_as_uint(Ks[(8*nt + g) * SK + 8*ks + t]);
                bb[1] = __float_as_uint(Ks[(8*nt + g) * SK + 8*ks + t + 4]);
                mma_tf32(sc[nt], qa[ks], bb);
            }
        }

        float mx0 = -1e30f, mx1 = -1e30f;
        const int colb = kt * 64 + 2 * t;
        #pragma unroll
        for (int nt = 0; nt < 8; nt++) {
            int c0 = colb + 8 * nt;
            float v0 = sc[nt][0]; if (c0     > row0) v0 = -1e30f;
            float v1 = sc[nt][1]; if (c0 + 1 > row0) v1 = -1e30f;
            float v2 = sc[nt][2]; if (c0     > row1) v2 = -1e30f;
            float v3 = sc[nt][3]; if (c0 + 1 > row1) v3 = -1e30f;
            sc[nt][0] = v0; sc[nt][1] = v1; sc[nt][2] = v2; sc[nt][3] = v3;
            mx0 = fmaxf(mx0, fmaxf(v0, v1));
            mx1 = fmaxf(mx1, fmaxf(v2, v3));
        }
        mx0 = fmaxf(mx0, __shfl_xor_sync(0xffffffffu, mx0, 1));
        mx0 = fmaxf(mx0, __shfl_xor_sync(0xffffffffu, mx0, 2));
        mx1 = fmaxf(mx1, __shfl_xor_sync(0xffffffffu, mx1, 1));
        mx1 = fmaxf(mx1, __shfl_xor_sync(0xffffffffu, mx1, 2));

        float mn0 = fmaxf(m0, mx0), mn1 = fmaxf(m1, mx1);
        float s0 = __expf(m0 - mn0), s1 = __expf(m1 - mn1);
        m0 = mn0; m1 = mn1;

        float sum0 = 0.f, sum1 = 0.f;
        #pragma unroll
        for (int nt = 0; nt < 8; nt++) {
            float p0 = __expf(sc[nt][0] - mn0);
            float p1 = __expf(sc[nt][1] - mn0);
            float p2 = __expf(sc[nt][2] - mn1);
            float p3 = __expf(sc[nt][3] - mn1);
            sum0 += p0 + p1; sum1 += p2 + p3;
            *(float2*)&Ps[(wrow + g)     * SK + 8*nt + 2*t] =
                make_float2(rnd_tf32(p0), rnd_tf32(p1));
            *(float2*)&Ps[(wrow + g + 8) * SK + 8*nt + 2*t] =
                make_float2(rnd_tf32(p2), rnd_tf32(p3));
        }
        sum0 += __shfl_xor_sync(0xffffffffu, sum0, 1);
        sum0 += __shfl_xor_sync(0xffffffffu, sum0, 2);
        sum1 += __shfl_xor_sync(0xffffffffu, sum1, 1);
        sum1 += __shfl_xor_sync(0xffffffffu, sum1, 2);
        l0 = l0 * s0 + sum0;
        l1 = l1 * s1 + sum1;

        #pragma unroll
        for (int nt = 0; nt < 8; nt++) {
            o[nt][0] *= s0; o[nt][1] *= s0;
            o[nt][2] *= s1; o[nt][3] *= s1;
        }
        __syncwarp();                          // P visible within warp

        // ---- O += P @ V
        #pragma unroll
        for (int ks = 0; ks < 8; ks++) {
            unsigned pa[4];
            pa[0] = __float_as_uint(Ps[(wrow + g)     * SK + 8*ks + t]);
            pa[1] = __float_as_uint(Ps[(wrow + g + 8) * SK + 8*ks + t]);
            pa[2] = __float_as_uint(Ps[(wrow + g)     * SK + 8*ks + t + 4]);
            pa[3] = __float_as_uint(Ps[(wrow + g + 8) * SK + 8*ks + t + 4]);
            #pragma unroll
            for (int nt = 0; nt < 8; nt++) {
                unsigned bb[2];
                bb[0] = __float_as_uint(Vs[(8*ks + t)     * SV + 8*nt + g]);
                bb[1] = __float_as_uint(Vs[(8*ks + t + 4) * SV + 8*nt + g]);
                mma_tf32(o[nt], pa, bb);
            }
        }
    }

    // epilogue: tf32-rounded, pos8-permuted (ctx feeds O-proj GEMM as A)
    float inv0 = __fdividef(1.f, l0), inv1 = __fdividef(1.f, l1);
    #pragma unroll
    for (int nt = 0; nt < 8; nt++) {
        int c0 = 8 * nt + 2 * t;
        cb[(size_t)row0 * D_ + POS8(c0)]     = rnd_tf32(o[nt][0] * inv0);
        cb[(size_t)row0 * D_ + POS8(c0 + 1)] = rnd_tf32(o[nt][1] * inv0);
        cb[(size_t)row1 * D_ + POS8(c0)]     = rnd_tf32(o[nt][2] * inv1);
        cb[(size_t)row1 * D_ + POS8(c0 + 1)] = rnd_tf32(o[nt][3] * inv1);
    }
}

// ---------------- launcher -------------------------------------------------------
extern "C" void kernel_launch(void* const* d_in, const int* in_sizes, int n_in,
                              void* d_out, int out_size)
{
    const float* x     = (const float*)d_in[0];
    const float* ln1_s = (const float*)d_in[1];
    const float* ln1_b = (const float*)d_in[2];
    const float* wq    = (const float*)d_in[3];
    const float* wk    = (const float*)d_in[4];
    const float* wv    = (const float*)d_in[5];
    const float* wo    = (const float*)d_in[6];
    const float* bo    = (const float*)d_in[7];
    const float* ln2_s = (const float*)d_in[8];
    const float* ln2_b = (const float*)d_in[9];
    const float* w1    = (const float*)d_in[10];
    const float* b1    = (const float*)d_in[11];
    const float* w2    = (const float*)d_in[12];
    const float* b2    = (const float*)d_in[13];
    float* out = (float*)d_out;

    float *ln, *qkv, *ctx, *h, *ffn, *pool;
    cudaGetSymbolAddress((void**)&ln,   g_ln);
    cudaGetSymbolAddress((void**)&qkv,  g_qkv);
    cudaGetSymbolAddress((void**)&ctx,  g_ctx);
    cudaGetSymbolAddress((void**)&h,    g_h);
    cudaGetSymbolAddress((void**)&ffn,  g_ffn);
    cudaGetSymbolAddress((void**)&pool, g_pool);

    const int MB = 1024 * 1024;
    float* wqkvT = pool + 0 * MB;   // [3072][1024] pos8
    float* woT   = pool + 3 * MB;   // [1024][1024] pos8
    float* w1T   = pool + 4 * MB;   // [4096][1024] pos8
    float* w2T   = pool + 8 * MB;   // [1024][4096] pos8

    cudaFuncSetAttribute(flash_attn_kernel,
                         cudaFuncAttributeMaxDynamicSharedMemorySize, FLASH_SMEM);
    cudaFuncSetAttribute(sgemm_tf32_kernel,
                         cudaFuncAttributeMaxDynamicSharedMemorySize, GEMM_SMEM);

    // 0) weight prep: transpose + pos8-perm + round (QKV packed into [3072][1024])
    transpose_round_kernel<<<dim3(D_/32,  D_/32),  256>>>(wq, wqkvT, D_, D_, 0);
    transpose_round_kernel<<<dim3(D_/32,  D_/32),  256>>>(wk, wqkvT, D_, D_, 1024);
    transpose_round_kernel<<<dim3(D_/32,  D_/32),  256>>>(wv, wqkvT, D_, D_, 2048);
    transpose_round_kernel<<<dim3(D_/32,  D_/32),  256>>>(wo, woT,  D_, D_, 0);
    transpose_round_kernel<<<dim3(DFF_/32, D_/32), 256>>>(w1, w1T,  D_, DFF_, 0);
    transpose_round_kernel<<<dim3(D_/32, DFF_/32), 256>>>(w2, w2T,  DFF_, D_, 0);

    // 1) ln1(x) -> pos8
    ln_kernel<<<M_, 256>>>(x, ln1_s, ln1_b, ln);

    // 2) fused QKV projection: out NORMAL layout (+round), feeds flash
    dim3 gqkv(QKVD / 128, M_ / 128);
    sgemm_tf32_kernel<<<gqkv, 128, GEMM_SMEM>>>(ln, wqkvT, nullptr, nullptr, qkv,
                                                M_, QKVD, D_, 0, 1, 0);

    // 3) fused flash attention -> ctx (rounded + pos8)
    flash_attn_kernel<<<dim3(S_/128, B_*H_), 256, FLASH_SMEM>>>(qkv, ctx);

    // 4) output projection + bias + residual -> h (normal, full precision)
    dim3 gp(D_ / 128, M_ / 128);
    sgemm_tf32_kernel<<<gp, 128, GEMM_SMEM>>>(ctx, woT, bo, x, h, M_, D_, D_, 0, 0, 0);

    // 5) ln2(h) -> pos8
    ln_kernel<<<M_, 256>>>(h, ln2_s, ln2_b, ln);

    // 6) FFN: ffn written rounded+pos8 (feeds FFN2 as A); final out normal
    dim3 gf1(DFF_ / 128, M_ / 128);
    sgemm_tf32_kernel<<<gf1, 128, GEMM_SMEM>>>(ln, w1T, b1, nullptr, ffn, M_, DFF_, D_, 1, 1, 1);
    sgemm_tf32_kernel<<<gp, 128, GEMM_SMEM>>>(ffn, w2T, b2, h, out, M_, D_, DFF_, 0, 0, 0);
}